// round 1
// baseline (speedup 1.0000x reference)
#include <cuda_runtime.h>
#include <math.h>

// Problem constants
#define BB 64
#define SS 64
#define TT 21
#define DD 512
#define VV 32000
#define BT (BB*TT)        // 1344
#define NTILE (VV/64)     // 500

// ---------------- static device scratch (no runtime allocation) ----------------
__device__ float g_cat[BB*640];        // [encode_hidden | style_feature]
__device__ float g_inp2[BB*1024];      // [context | h]
__device__ float g_q[BB*512];          // attention query h @ attn_W
__device__ float g_gates[BB*2048];
__device__ float g_c[BB*512];
__device__ float g_emb[BT*512];        // emb_table[decoder_input]
__device__ float g_xproj[BT*2048];     // emb @ W_ih_emb^T + b_ih + b_hh
__device__ float g_wcomb[2048*1024];   // [W_ih_ctx | W_hh]
__device__ float g_biassum[2048];
__device__ float g_outs[BT*512];       // LSTM hidden outputs
__device__ float g_pmax[BT*NTILE];     // per (row, vocab-tile) partial max
__device__ float g_psum[BT*NTILE];     // per (row, vocab-tile) partial sumexp
__device__ float g_lab[BT];            // logit at label
__device__ float g_nll[BT];            // masked nll per (b,t)

// ---------------- generic tiled fp32 GEMM ----------------
// C[M,N] (+)= A[M,K] @ op(B)  (+ bias[n]) (+ addf[m,n])
// TRANSB: B is (N,K) row-major; else B is (K,N) row-major.
// ATOMIC: atomicAdd into C (split-K path; bias/addf ignored; C must be pre-inited).
// kbeg = blockIdx.z * klen. M,N multiples of 64; klen multiple of 32.
template<bool TRANSB, bool ATOMIC>
__global__ void gemm_kernel(int klen,
                            const float* __restrict__ A, int lda,
                            const float* __restrict__ B, int ldb,
                            float* __restrict__ C, int ldc,
                            const float* __restrict__ bias,
                            const float* __restrict__ addf, int ldd)
{
    __shared__ float As[32][68];
    __shared__ float Bs[32][68];
    const int bm = blockIdx.y * 64;
    const int bn = blockIdx.x * 64;
    const int kbeg = blockIdx.z * klen;
    const int tid = threadIdx.x;
    const int tm = (tid >> 4) << 2;
    const int tn = (tid & 15) << 2;
    float acc[4][4] = {};

    for (int k0 = kbeg; k0 < kbeg + klen; k0 += 32) {
#pragma unroll
        for (int i = 0; i < 8; i++) {
            int e = tid + i * 256;
            int m = e >> 5, k = e & 31;
            As[k][m] = A[(size_t)(bm + m) * lda + k0 + k];
        }
        if (TRANSB) {
#pragma unroll
            for (int i = 0; i < 8; i++) {
                int e = tid + i * 256;
                int n = e >> 5, k = e & 31;
                Bs[k][n] = B[(size_t)(bn + n) * ldb + k0 + k];
            }
        } else {
#pragma unroll
            for (int i = 0; i < 8; i++) {
                int e = tid + i * 256;
                int k = e >> 6, n = e & 63;
                Bs[k][n] = B[(size_t)(k0 + k) * ldb + bn + n];
            }
        }
        __syncthreads();
#pragma unroll
        for (int k = 0; k < 32; k++) {
            float4 av = *reinterpret_cast<const float4*>(&As[k][tm]);
            float4 bv = *reinterpret_cast<const float4*>(&Bs[k][tn]);
            float a_[4] = {av.x, av.y, av.z, av.w};
            float b_[4] = {bv.x, bv.y, bv.z, bv.w};
#pragma unroll
            for (int i = 0; i < 4; i++)
#pragma unroll
                for (int j = 0; j < 4; j++)
                    acc[i][j] += a_[i] * b_[j];
        }
        __syncthreads();
    }

    if (ATOMIC) {
#pragma unroll
        for (int i = 0; i < 4; i++) {
            size_t ro = (size_t)(bm + tm + i);
#pragma unroll
            for (int j = 0; j < 4; j++)
                atomicAdd(&C[ro * ldc + bn + tn + j], acc[i][j]);
        }
    } else {
#pragma unroll
        for (int i = 0; i < 4; i++) {
            size_t ro = (size_t)(bm + tm + i);
#pragma unroll
            for (int j = 0; j < 4; j++) {
                float v = acc[i][j];
                int n = bn + tn + j;
                if (bias) v += bias[n];
                if (addf) v += addf[ro * ldd + n];
                C[ro * ldc + n] = v;
            }
        }
    }
}

// ---------------- projection GEMM fused with per-tile logsumexp partials ----------------
// logits tile = outs[64,512] @ proj_w[64,512]^T + proj_b; emit per-row (max, sumexp).
__global__ void proj_lse_kernel(const float* __restrict__ Bw, const float* __restrict__ pb)
{
    __shared__ float As[32][68];
    __shared__ float Bs[32][68];
    const int bm = blockIdx.y * 64;
    const int bn = blockIdx.x * 64;
    const int tid = threadIdx.x;
    const int tm = (tid >> 4) << 2;
    const int tn = (tid & 15) << 2;
    float acc[4][4] = {};

    for (int k0 = 0; k0 < 512; k0 += 32) {
#pragma unroll
        for (int i = 0; i < 8; i++) {
            int e = tid + i * 256;
            int m = e >> 5, k = e & 31;
            As[k][m] = g_outs[(size_t)(bm + m) * 512 + k0 + k];
        }
#pragma unroll
        for (int i = 0; i < 8; i++) {
            int e = tid + i * 256;
            int n = e >> 5, k = e & 31;
            Bs[k][n] = Bw[(size_t)(bn + n) * 512 + k0 + k];
        }
        __syncthreads();
#pragma unroll
        for (int k = 0; k < 32; k++) {
            float4 av = *reinterpret_cast<const float4*>(&As[k][tm]);
            float4 bv = *reinterpret_cast<const float4*>(&Bs[k][tn]);
            float a_[4] = {av.x, av.y, av.z, av.w};
            float b_[4] = {bv.x, bv.y, bv.z, bv.w};
#pragma unroll
            for (int i = 0; i < 4; i++)
#pragma unroll
                for (int j = 0; j < 4; j++)
                    acc[i][j] += a_[i] * b_[j];
        }
        __syncthreads();
    }

    float bj[4];
#pragma unroll
    for (int j = 0; j < 4; j++) bj[j] = pb[bn + tn + j];
#pragma unroll
    for (int i = 0; i < 4; i++)
#pragma unroll
        for (int j = 0; j < 4; j++) acc[i][j] += bj[j];

    // per output-row reduction across the 16 threads (and 4 cols each) of the row group
#pragma unroll
    for (int i = 0; i < 4; i++) {
        float m = fmaxf(fmaxf(acc[i][0], acc[i][1]), fmaxf(acc[i][2], acc[i][3]));
#pragma unroll
        for (int o = 8; o; o >>= 1) m = fmaxf(m, __shfl_xor_sync(0xffffffffu, m, o));
        float se = expf(acc[i][0] - m) + expf(acc[i][1] - m)
                 + expf(acc[i][2] - m) + expf(acc[i][3] - m);
#pragma unroll
        for (int o = 8; o; o >>= 1) se += __shfl_xor_sync(0xffffffffu, se, o);
        if ((tid & 15) == 0) {
            int row = bm + tm + i;
            g_pmax[(size_t)row * NTILE + blockIdx.x] = m;
            g_psum[(size_t)row * NTILE + blockIdx.x] = se;
        }
    }
}

// ---------------- per-step attention (scores -> softmax -> context) ----------------
// Also pre-initializes g_gates with xproj_t (so the split-K gates GEMM can atomicAdd).
__global__ void attn_kernel(const float* __restrict__ enc, int t)
{
    __shared__ float qs[512];
    __shared__ float sc[64];
    __shared__ float s_inv;
    const int b = blockIdx.x, tid = threadIdx.x;

    qs[tid]       = g_q[b * 512 + tid];
    qs[tid + 256] = g_q[b * 512 + 256 + tid];
    size_t xo = (size_t)(b * TT + t) * 2048;
#pragma unroll
    for (int i = 0; i < 8; i++)
        g_gates[b * 2048 + tid + i * 256] = g_xproj[xo + tid + i * 256];
    __syncthreads();

    const int w = tid >> 5, lane = tid & 31;
    const float* eb = enc + (size_t)b * SS * DD;
    for (int s = w; s < SS; s += 8) {
        const float* er = eb + (size_t)s * DD;
        float a = 0.f;
        for (int k = lane; k < DD; k += 32) a += qs[k] * er[k];
#pragma unroll
        for (int o = 16; o; o >>= 1) a += __shfl_xor_sync(0xffffffffu, a, o);
        if (lane == 0) sc[s] = a;
    }
    __syncthreads();

    if (w == 0) {
        float v0 = sc[lane], v1 = sc[lane + 32];
        float m = fmaxf(v0, v1);
#pragma unroll
        for (int o = 16; o; o >>= 1) m = fmaxf(m, __shfl_xor_sync(0xffffffffu, m, o));
        float e0 = expf(v0 - m), e1 = expf(v1 - m);
        float ss = e0 + e1;
#pragma unroll
        for (int o = 16; o; o >>= 1) ss += __shfl_xor_sync(0xffffffffu, ss, o);
        sc[lane] = e0; sc[lane + 32] = e1;
        if (lane == 0) s_inv = 1.f / ss;
    }
    __syncthreads();

    float inv = s_inv;
    for (int d = tid; d < DD; d += 256) {
        float a = 0.f;
#pragma unroll 8
        for (int s = 0; s < SS; s++) a += sc[s] * eb[(size_t)s * DD + d];
        g_inp2[b * 1024 + d] = a * inv;  // context into first half of inp2
    }
}

// ---------------- per-step LSTM pointwise ----------------
__global__ void pointwise_kernel(int t)
{
    const int b = blockIdx.x, j = threadIdx.x;
    const int gb = b * 2048;
    float gi = g_gates[gb + j];
    float gf = g_gates[gb + 512 + j];
    float gg = g_gates[gb + 1024 + j];
    float go = g_gates[gb + 1536 + j];
    float c = g_c[b * 512 + j];
    float si = 1.f / (1.f + expf(-gi));
    float sf = 1.f / (1.f + expf(-gf));
    float so = 1.f / (1.f + expf(-go));
    c = sf * c + si * tanhf(gg);
    g_c[b * 512 + j] = c;
    float h = so * tanhf(c);
    g_outs[(size_t)(b * TT + t) * 512 + j] = h;
    g_inp2[b * 1024 + 512 + j] = h;   // h half of inp2 for next step
    g_q[b * 512 + j] = 0.f;           // zero accumulator for next step's split-K q GEMM
}

// ---------------- one-time prep kernels ----------------
__global__ void prep_small_kernel(const float* __restrict__ eh, const float* __restrict__ st,
                                  const float* __restrict__ bih, const float* __restrict__ bhh)
{
    int i = blockIdx.x * blockDim.x + threadIdx.x;
    if (i < BB * 640) {
        int b = i / 640, j = i - b * 640;
        g_cat[i] = (j < 512) ? eh[b * 512 + j] : st[b * 512 + (j - 128)]; // style_emb[b,3,j-512]
    } else if (i < BB * 640 + 2048) {
        int j = i - BB * 640;
        g_biassum[j] = bih[j] + bhh[j];
    } else if (i < BB * 640 + 2048 + BB * 512) {
        g_c[i - (BB * 640 + 2048)] = 0.f;
    } else if (i < BB * 640 + 2048 + 2 * BB * 512) {
        g_q[i - (BB * 640 + 2048 + BB * 512)] = 0.f;
    }
}

__global__ void wcomb_kernel(const float* __restrict__ wih, const float* __restrict__ whh)
{
    int i = blockIdx.x * blockDim.x + threadIdx.x;  // 2048 * 1024 threads
    int r = i >> 10, c = i & 1023;
    g_wcomb[i] = (c < 512) ? wih[(size_t)r * 1024 + c] : whh[(size_t)r * 512 + (c - 512)];
}

__global__ void embed_kernel(const int* __restrict__ di, const float* __restrict__ et)
{
    int row = blockIdx.x, tid = threadIdx.x;
    int idx = di[row];
    g_emb[(size_t)row * 512 + tid] = et[(size_t)idx * 512 + tid];
}

// ---------------- loss ----------------
__global__ void lablogit_kernel(const int* __restrict__ lab, const float* __restrict__ pw,
                                const float* __restrict__ pb)
{
    int gt = blockIdx.x * blockDim.x + threadIdx.x;
    int w = gt >> 5, lane = gt & 31;
    if (w >= BT) return;
    int l = lab[w];
    const float* o  = g_outs + (size_t)w * 512;
    const float* wr = pw + (size_t)l * 512;
    float a = 0.f;
    for (int k = lane; k < 512; k += 32) a += o[k] * wr[k];
#pragma unroll
    for (int off = 16; off; off >>= 1) a += __shfl_xor_sync(0xffffffffu, a, off);
    if (lane == 0) g_lab[w] = a + pb[l];
}

__global__ void loss_row_kernel(const int* __restrict__ lab)
{
    __shared__ float red[128];
    const int r = blockIdx.x, tid = threadIdx.x;
    const float* pm = g_pmax + (size_t)r * NTILE;
    const float* ps = g_psum + (size_t)r * NTILE;
    float m = -1e30f;
    for (int j = tid; j < NTILE; j += 128) m = fmaxf(m, pm[j]);
    red[tid] = m; __syncthreads();
    for (int s = 64; s; s >>= 1) { if (tid < s) red[tid] = fmaxf(red[tid], red[tid + s]); __syncthreads(); }
    float M = red[0]; __syncthreads();
    float se = 0.f;
    for (int j = tid; j < NTILE; j += 128) se += ps[j] * expf(pm[j] - M);
    red[tid] = se; __syncthreads();
    for (int s = 64; s; s >>= 1) { if (tid < s) red[tid] += red[tid + s]; __syncthreads(); }
    if (tid == 0) {
        float lse = M + logf(red[0]);
        int l = lab[r];
        g_nll[r] = (l > 0) ? (lse - g_lab[r]) : 0.f;
    }
}

__global__ void loss_final_kernel(const int* __restrict__ lab, float* __restrict__ out)
{
    __shared__ float red[64];
    const int b = threadIdx.x;
    float s = 0.f, cnt = 0.f;
    for (int t = 0; t < TT; t++) {
        int r = b * TT + t;
        s += g_nll[r];
        cnt += (lab[r] > 0) ? 1.f : 0.f;
    }
    red[b] = s / (cnt + 1e-6f);
    __syncthreads();
    if (b == 0) {
        float a = 0.f;
        for (int i = 0; i < 64; i++) a += red[i];
        out[0] = a / 64.f;
    }
}

// ---------------- host launcher ----------------
extern "C" void kernel_launch(void* const* d_in, const int* in_sizes, int n_in,
                              void* d_out, int out_size)
{
    const float* encode_hidden = (const float*)d_in[0];
    const float* encode_output = (const float*)d_in[1];
    /* d_in[2] encoder_mask: unused by the reference computation */
    const int*   seq_label     = (const int*)  d_in[3];
    const int*   decoder_input = (const int*)  d_in[4];
    const float* style_emb     = (const float*)d_in[5];
    const float* w_e2d         = (const float*)d_in[6];
    const float* b_e2d         = (const float*)d_in[7];
    const float* attn_W        = (const float*)d_in[8];
    const float* emb_table     = (const float*)d_in[9];
    const float* w_ih          = (const float*)d_in[10];
    const float* w_hh          = (const float*)d_in[11];
    const float* b_ih          = (const float*)d_in[12];
    const float* b_hh          = (const float*)d_in[13];
    const float* proj_w        = (const float*)d_in[14];
    const float* proj_b        = (const float*)d_in[15];
    float* out = (float*)d_out;

    float *p_cat, *p_inp2, *p_q, *p_gates, *p_emb, *p_xproj, *p_wcomb, *p_biassum;
    cudaGetSymbolAddress((void**)&p_cat,     g_cat);
    cudaGetSymbolAddress((void**)&p_inp2,    g_inp2);
    cudaGetSymbolAddress((void**)&p_q,       g_q);
    cudaGetSymbolAddress((void**)&p_gates,   g_gates);
    cudaGetSymbolAddress((void**)&p_emb,     g_emb);
    cudaGetSymbolAddress((void**)&p_xproj,   g_xproj);
    cudaGetSymbolAddress((void**)&p_wcomb,   g_wcomb);
    cudaGetSymbolAddress((void**)&p_biassum, g_biassum);

    // one-time prep
    prep_small_kernel<<<424, 256>>>(encode_hidden, style_emb, b_ih, b_hh);
    wcomb_kernel<<<2048, 1024>>>(w_ih, w_hh);
    embed_kernel<<<BT, 512>>>(decoder_input, emb_table);

    // h0 = cat @ W_e2d^T + b  -> h half of inp2
    gemm_kernel<true, false><<<dim3(8, 1, 1), 256>>>(640,
        p_cat, 640, w_e2d, 640, p_inp2 + 512, 1024, b_e2d, nullptr, 0);

    // xproj = emb @ W_ih_emb^T + (b_ih + b_hh)
    gemm_kernel<true, false><<<dim3(32, 21, 1), 256>>>(512,
        p_emb, 512, w_ih + 512, 1024, p_xproj, 2048, p_biassum, nullptr, 0);

    for (int t = 0; t < TT; t++) {
        // q = h @ attn_W   (split-K, atomic into zeroed g_q)
        gemm_kernel<false, true><<<dim3(8, 1, 8), 256>>>(64,
            p_inp2 + 512, 1024, attn_W, 512, p_q, 512, nullptr, nullptr, 0);
        // attention scores/softmax/context; also inits g_gates = xproj_t
        attn_kernel<<<64, 256>>>(encode_output, t);
        // gates += [ctx|h] @ [W_ih_ctx|W_hh]^T   (split-K atomic)
        gemm_kernel<true, true><<<dim3(32, 1, 4), 256>>>(256,
            p_inp2, 1024, p_wcomb, 1024, p_gates, 2048, nullptr, nullptr, 0);
        // LSTM cell update, write outs, refresh h, zero q for next step
        pointwise_kernel<<<64, 512>>>(t);
    }

    // loss: label logits, fused projection+partial logsumexp, row reduce, final mean
    lablogit_kernel<<<168, 256>>>(seq_label, proj_w, proj_b);
    proj_lse_kernel<<<dim3(NTILE, 21), 256>>>(proj_w, proj_b);
    loss_row_kernel<<<BT, 128>>>(seq_label);
    loss_final_kernel<<<1, 64>>>(seq_label, out);
}